// round 6
// baseline (speedup 1.0000x reference)
#include <cuda_runtime.h>
#include <cstdint>

// GlobalContextAttention — fused, cp.async.bulk double-buffered staging.
// x (J, F, C=128) fp32, batch_index (F,) int32 SORTED, weight (C,C) fp32 -> out (J, B, C).
//
// R5 lesson: latency-bound at 56% DRAM; in-flight bytes capped by regs/warps.
// Fix: one thread issues 24KB bulk copies (48 frames) into 2 smem buffers per
// pass; warps consume from smem. In-flight/SM ~96KB (4 CTAs x 24KB) vs 32KB.
// Occupancy stays 4 CTAs/SM (54KB smem) so pass2's re-fetch still hits L2
// (live footprint ~90MB < 126MB).

static constexpr int C_DIM   = 128;
static constexpr int THREADS = 256;
static constexpr int WARPS   = 8;
static constexpr int CHUNK   = 48;                    // frames per chunk = 24 KB
static constexpr int MAX_SEG = 4096;
static constexpr int BUF_FLOATS = 2 * CHUNK * C_DIM;  // 12288
static constexpr int SMEM_BYTES = (BUF_FLOATS + WARPS * C_DIM + C_DIM) * 4 + 64;

__device__ int g_seg[MAX_SEG + 1];

__global__ void seg_bounds_kernel(const int* __restrict__ idx, int Fn, int Bn)
{
    const int t = blockIdx.x * blockDim.x + threadIdx.x;
    if (t > Bn) return;
    int lo = 0, hi = Fn;
    while (lo < hi) {
        int m = (lo + hi) >> 1;
        if (idx[m] < t) lo = m + 1; else hi = m;
    }
    g_seg[t] = lo;
}

__device__ __forceinline__ uint32_t s2u(const void* p) {
    uint32_t a;
    asm("{ .reg .u64 t; cvta.to.shared.u64 t, %1; cvt.u32.u64 %0, t; }" : "=r"(a) : "l"(p));
    return a;
}
__device__ __forceinline__ void mbar_init(uint32_t m) {
    asm volatile("mbarrier.init.shared.b64 [%0], 1;" :: "r"(m) : "memory");
}
__device__ __forceinline__ void mbar_expect(uint32_t m, uint32_t bytes) {
    asm volatile("mbarrier.arrive.expect_tx.shared.b64 _, [%0], %1;" :: "r"(m), "r"(bytes) : "memory");
}
__device__ __forceinline__ void mbar_wait(uint32_t m, uint32_t parity) {
    asm volatile(
        "{\n\t"
        ".reg .pred P;\n\t"
        "WAIT_%=:\n\t"
        "mbarrier.try_wait.parity.acquire.cta.shared::cta.b64 P, [%0], %1, 0x989680;\n\t"
        "@P bra.uni DONE_%=;\n\t"
        "bra.uni WAIT_%=;\n\t"
        "DONE_%=:\n\t"
        "}"
        :: "r"(m), "r"(parity) : "memory");
}
__device__ __forceinline__ void bulk_cp(uint32_t dst, const float* src, uint32_t bytes, uint32_t m) {
    asm volatile(
        "cp.async.bulk.shared::cluster.global.mbarrier::complete_tx::bytes [%0], [%1], %2, [%3];"
        :: "r"(dst), "l"(src), "r"(bytes), "r"(m) : "memory");
}

__global__ __launch_bounds__(THREADS, 4)
void gca_fused_kernel(const float* __restrict__ x,
                      const float* __restrict__ W,
                      float*       __restrict__ out,
                      int Jn, int Fn, int Bn)
{
    extern __shared__ float dyn[];
    float* buf   = dyn;                       // 2 x CHUNK x 128
    float* s_red = dyn + BUF_FLOATS;          // WARPS x 128
    float* s_vec = s_red + WARPS * C_DIM;     // 128  (mean, then gc)
    const uint32_t mb = s2u(s_vec + C_DIM);   // 4 mbarriers (8B each)

    const int tid  = threadIdx.x;
    const int warp = tid >> 5;
    const int lane = tid & 31;
    const int b    = blockIdx.x;
    const int j    = blockIdx.y;

    if (tid < 4) mbar_init(mb + tid * 8);
    __syncthreads();

    const int start = g_seg[b];
    const int end   = g_seg[b + 1];
    const int cnt   = end - start;
    const float inv_cnt = 1.0f / (float)(cnt > 0 ? cnt : 1);
    const int ch = lane * 4;
    const float* xseg = x + ((size_t)j * Fn + start) * C_DIM;
    const int nch = (cnt + CHUNK - 1) / CHUNK;

    // ---------------- pass 1: segment sum (pipelined bulk copies, mbars 0/1) ----
    if (tid == 0) {
        const int pre = nch < 2 ? nch : 2;
        for (int c = 0; c < pre; c++) {
            const int csz = min(CHUNK, cnt - c * CHUNK);
            const uint32_t bytes = (uint32_t)csz * C_DIM * 4;
            mbar_expect(mb + (c & 1) * 8, bytes);
            bulk_cp(s2u(buf + (c & 1) * CHUNK * C_DIM),
                    xseg + (size_t)c * CHUNK * C_DIM, bytes, mb + (c & 1) * 8);
        }
    }
    float4 acc = make_float4(0.f, 0.f, 0.f, 0.f);
    for (int c = 0; c < nch; c++) {
        mbar_wait(mb + (c & 1) * 8, (c >> 1) & 1);
        const int csz = min(CHUNK, cnt - c * CHUNK);
        const float* bb = buf + (c & 1) * CHUNK * C_DIM;
        for (int fl = warp; fl < csz; fl += WARPS) {
            const float4 a = *(const float4*)(bb + fl * C_DIM + ch);
            acc.x += a.x; acc.y += a.y; acc.z += a.z; acc.w += a.w;
        }
        __syncthreads();                       // all consumers done with this slot
        if (tid == 0 && c + 2 < nch) {
            const int c2 = c + 2;
            const uint32_t bytes = (uint32_t)min(CHUNK, cnt - c2 * CHUNK) * C_DIM * 4;
            mbar_expect(mb + (c & 1) * 8, bytes);
            bulk_cp(s2u(buf + (c & 1) * CHUNK * C_DIM),
                    xseg + (size_t)c2 * CHUNK * C_DIM, bytes, mb + (c & 1) * 8);
        }
    }

    // Prefetch pass-2 chunks 0/1 now (mbars 2/3) so they land under the GEMV.
    if (tid == 0) {
        const int pre = nch < 2 ? nch : 2;
        for (int c = 0; c < pre; c++) {
            const int csz = min(CHUNK, cnt - c * CHUNK);
            const uint32_t bytes = (uint32_t)csz * C_DIM * 4;
            mbar_expect(mb + 16 + (c & 1) * 8, bytes);
            bulk_cp(s2u(buf + (c & 1) * CHUNK * C_DIM),
                    xseg + (size_t)c * CHUNK * C_DIM, bytes, mb + 16 + (c & 1) * 8);
        }
    }

    // reduce to mean
    *(float4*)&s_red[warp * C_DIM + ch] = acc;
    __syncthreads();
    if (tid < C_DIM) {
        float s = 0.f;
#pragma unroll
        for (int w = 0; w < WARPS; w++) s += s_red[w * C_DIM + tid];
        s_vec[tid] = s * inv_cnt;              // mean[j,b,:]
    }
    __syncthreads();

    // ---------------- GEMV: gc = tanh(mean @ W) ----------------
    {
        const int t_out = tid & (C_DIM - 1);
        const int half  = tid >> 7;            // 0..1
        const float* wp = W + (size_t)(half * 64) * C_DIM + t_out;
        float p = 0.f;
#pragma unroll 8
        for (int k = 0; k < 64; k++)
            p += s_vec[half * 64 + k] * wp[(size_t)k * C_DIM];
        s_red[half * C_DIM + t_out] = p;
    }
    __syncthreads();
    if (tid < C_DIM)
        s_vec[tid] = tanhf(s_red[tid] + s_red[C_DIM + tid]);
    __syncthreads();

    // ---------------- pass 2: gate + gated segment mean (mbars 2/3) ----------
    const float4 gc4 = *(const float4*)&s_vec[ch];
    float4 oacc = make_float4(0.f, 0.f, 0.f, 0.f);
    for (int c = 0; c < nch; c++) {
        mbar_wait(mb + 16 + (c & 1) * 8, (c >> 1) & 1);
        const int csz = min(CHUNK, cnt - c * CHUNK);
        const float* bb = buf + (c & 1) * CHUNK * C_DIM;
        for (int fl = warp; fl < csz; fl += WARPS) {
            const float4 a = *(const float4*)(bb + fl * C_DIM + ch);
            float d = a.x * gc4.x + a.y * gc4.y + a.z * gc4.z + a.w * gc4.w;
#pragma unroll
            for (int s = 16; s > 0; s >>= 1)
                d += __shfl_xor_sync(0xffffffffu, d, s);
            const float g = 1.f / (1.f + __expf(-d));
            oacc.x += g * a.x; oacc.y += g * a.y; oacc.z += g * a.z; oacc.w += g * a.w;
        }
        __syncthreads();
        if (tid == 0 && c + 2 < nch) {
            const int c2 = c + 2;
            const uint32_t bytes = (uint32_t)min(CHUNK, cnt - c2 * CHUNK) * C_DIM * 4;
            mbar_expect(mb + 16 + (c & 1) * 8, bytes);
            bulk_cp(s2u(buf + (c & 1) * CHUNK * C_DIM),
                    xseg + (size_t)c2 * CHUNK * C_DIM, bytes, mb + 16 + (c & 1) * 8);
        }
    }

    *(float4*)&s_red[warp * C_DIM + ch] = oacc;
    __syncthreads();
    if (tid < C_DIM) {
        float s = 0.f;
#pragma unroll
        for (int w = 0; w < WARPS; w++) s += s_red[w * C_DIM + tid];
        out[((size_t)j * Bn + b) * C_DIM + tid] = s * inv_cnt;
    }
}

extern "C" void kernel_launch(void* const* d_in, const int* in_sizes, int n_in,
                              void* d_out, int out_size)
{
    // Identify inputs by element count: x = largest; weight = C*C; idx = other multi-element.
    int xi = 0;
    for (int i = 1; i < n_in; i++)
        if (in_sizes[i] > in_sizes[xi]) xi = i;
    int wi = -1, ii = -1;
    for (int i = 0; i < n_in; i++) {
        if (i == xi) continue;
        if (in_sizes[i] == C_DIM * C_DIM && wi < 0) { wi = i; continue; }
        if (in_sizes[i] > 1 && ii < 0) ii = i;
    }
    if (wi < 0 || ii < 0) return;

    const float* x   = (const float*)d_in[xi];
    const int*   idx = (const int*)  d_in[ii];
    const float* W   = (const float*)d_in[wi];
    float*       out = (float*)d_out;

    const int Fn = in_sizes[ii];
    const int Jn = in_sizes[xi] / (Fn * C_DIM);
    int Bn = out_size / (Jn * C_DIM);
    if (Bn > MAX_SEG) Bn = MAX_SEG;

    static bool attr_set = false;
    if (!attr_set) {
        cudaFuncSetAttribute(gca_fused_kernel,
                             cudaFuncAttributeMaxDynamicSharedMemorySize, SMEM_BYTES);
        attr_set = true;
    }

    seg_bounds_kernel<<<(Bn + THREADS) / THREADS + 1, THREADS>>>(idx, Fn, Bn);
    dim3 grid(Bn, Jn);
    gca_fused_kernel<<<grid, THREADS, SMEM_BYTES>>>(x, W, out, Jn, Fn, Bn);
}

// round 7
// speedup vs baseline: 1.0998x; 1.0998x over previous
#include <cuda_runtime.h>

// GlobalContextAttention — fused; wide CTAs decouple occupancy from L2 footprint.
// x (J, F, C=128) fp32, batch_index (F,) int32 SORTED, weight (C,C) fp32 -> out (J, B, C).
//
// R4 showed 48 warps/SM sustains 5.8TB/s; R5 showed 4 work-items/SM keeps pass2
// in L2 (x read once). Decouple the two: 512-thread CTAs (16 warps per work
// item), 3 CTAs/SM -> 48 warps/SM AND only 3 live slices/SM (~67MB chip-wide
// footprint < 126MB L2). Occupancy pinned by 64KB dynamic smem.

static constexpr int C_DIM   = 128;
static constexpr int THREADS = 512;
static constexpr int WARPS   = 16;
static constexpr int MAX_SEG = 4096;
static constexpr int SMEM_BYTES = 64 * 1024;   // pins exactly 3 CTAs/SM (228/64 = 3)

__device__ int g_seg[MAX_SEG + 1];

__global__ void seg_bounds_kernel(const int* __restrict__ idx, int Fn, int Bn)
{
    const int t = blockIdx.x * blockDim.x + threadIdx.x;
    if (t > Bn) return;
    int lo = 0, hi = Fn;
    while (lo < hi) {
        int m = (lo + hi) >> 1;
        if (idx[m] < t) lo = m + 1; else hi = m;
    }
    g_seg[t] = lo;
}

__global__ __launch_bounds__(THREADS, 3)
void gca_fused_kernel(const float* __restrict__ x,
                      const float* __restrict__ W,
                      float*       __restrict__ out,
                      int Jn, int Fn, int Bn)
{
    extern __shared__ float dyn[];
    float* s_red = dyn;                    // WARPS x 128 = 8 KB
    float* s_vec = dyn + WARPS * C_DIM;    // 128 (mean, then gc)

    const int tid  = threadIdx.x;
    const int warp = tid >> 5;
    const int lane = tid & 31;
    const int b    = blockIdx.x;
    const int j    = blockIdx.y;

    const int start = g_seg[b];
    const int end   = g_seg[b + 1];
    const int cnt   = end - start;
    const float inv_cnt = 1.0f / (float)(cnt > 0 ? cnt : 1);
    const int ch = lane * 4;               // this lane's float4 channel group
    const float* xj = x + (size_t)j * Fn * C_DIM;

    // ---------------- pass 1: per-channel segment sum (unroll 6) ----------------
    float4 acc = make_float4(0.f, 0.f, 0.f, 0.f);
    int f = start + warp;
    for (; f + 5 * WARPS < end; f += 6 * WARPS) {
#pragma unroll
        for (int u = 0; u < 6; u++) {
            const float4 a = *(const float4*)(xj + (size_t)(f + u * WARPS) * C_DIM + ch);
            acc.x += a.x; acc.y += a.y; acc.z += a.z; acc.w += a.w;
        }
    }
    for (; f < end; f += WARPS) {
        const float4 a = *(const float4*)(xj + (size_t)f * C_DIM + ch);
        acc.x += a.x; acc.y += a.y; acc.z += a.z; acc.w += a.w;
    }
    *(float4*)&s_red[warp * C_DIM + ch] = acc;
    __syncthreads();
    if (tid < C_DIM) {
        float s = 0.f;
#pragma unroll
        for (int w = 0; w < WARPS; w++) s += s_red[w * C_DIM + tid];
        s_vec[tid] = s * inv_cnt;          // mean[j,b,:]
    }
    __syncthreads();

    // ---------------- GEMV: gc = tanh(mean @ W), k split across 4 quarters ----
    {
        const int t_out = tid & (C_DIM - 1);
        const int q     = tid >> 7;        // 0..3
        const float* wp = W + (size_t)(q * 32) * C_DIM + t_out;
        float p = 0.f;
#pragma unroll 8
        for (int k = 0; k < 32; k++)
            p += s_vec[q * 32 + k] * wp[(size_t)k * C_DIM];
        s_red[q * C_DIM + t_out] = p;
    }
    __syncthreads();
    if (tid < C_DIM)
        s_vec[tid] = tanhf(s_red[tid] + s_red[C_DIM + tid] +
                           s_red[2 * C_DIM + tid] + s_red[3 * C_DIM + tid]);
    __syncthreads();

    // ---------------- pass 2: gate + gated segment mean (unroll 4) -------------
    const float4 gc4 = *(const float4*)&s_vec[ch];
    float4 oacc = make_float4(0.f, 0.f, 0.f, 0.f);
    f = start + warp;
    for (; f + 3 * WARPS < end; f += 4 * WARPS) {
        float4 a[4];
#pragma unroll
        for (int u = 0; u < 4; u++)
            a[u] = *(const float4*)(xj + (size_t)(f + u * WARPS) * C_DIM + ch);
        float d[4];
#pragma unroll
        for (int u = 0; u < 4; u++)
            d[u] = a[u].x*gc4.x + a[u].y*gc4.y + a[u].z*gc4.z + a[u].w*gc4.w;
#pragma unroll
        for (int s = 16; s > 0; s >>= 1) {
#pragma unroll
            for (int u = 0; u < 4; u++)
                d[u] += __shfl_xor_sync(0xffffffffu, d[u], s);
        }
#pragma unroll
        for (int u = 0; u < 4; u++) {
            const float g = 1.f / (1.f + __expf(-d[u]));
            oacc.x += g*a[u].x; oacc.y += g*a[u].y; oacc.z += g*a[u].z; oacc.w += g*a[u].w;
        }
    }
    for (; f < end; f += WARPS) {
        const float4 a = *(const float4*)(xj + (size_t)f * C_DIM + ch);
        float d = a.x*gc4.x + a.y*gc4.y + a.z*gc4.z + a.w*gc4.w;
#pragma unroll
        for (int s = 16; s > 0; s >>= 1)
            d += __shfl_xor_sync(0xffffffffu, d, s);
        const float g = 1.f / (1.f + __expf(-d));
        oacc.x += g*a.x; oacc.y += g*a.y; oacc.z += g*a.z; oacc.w += g*a.w;
    }
    *(float4*)&s_red[warp * C_DIM + ch] = oacc;
    __syncthreads();
    if (tid < C_DIM) {
        float s = 0.f;
#pragma unroll
        for (int w = 0; w < WARPS; w++) s += s_red[w * C_DIM + tid];
        out[((size_t)j * Bn + b) * C_DIM + tid] = s * inv_cnt;
    }
}

extern "C" void kernel_launch(void* const* d_in, const int* in_sizes, int n_in,
                              void* d_out, int out_size)
{
    // Identify inputs by element count: x = largest; weight = C*C; idx = other multi-element.
    int xi = 0;
    for (int i = 1; i < n_in; i++)
        if (in_sizes[i] > in_sizes[xi]) xi = i;
    int wi = -1, ii = -1;
    for (int i = 0; i < n_in; i++) {
        if (i == xi) continue;
        if (in_sizes[i] == C_DIM * C_DIM && wi < 0) { wi = i; continue; }
        if (in_sizes[i] > 1 && ii < 0) ii = i;
    }
    if (wi < 0 || ii < 0) return;

    const float* x   = (const float*)d_in[xi];
    const int*   idx = (const int*)  d_in[ii];
    const float* W   = (const float*)d_in[wi];
    float*       out = (float*)d_out;

    const int Fn = in_sizes[ii];
    const int Jn = in_sizes[xi] / (Fn * C_DIM);
    int Bn = out_size / (Jn * C_DIM);
    if (Bn > MAX_SEG) Bn = MAX_SEG;

    static bool attr_set = false;
    if (!attr_set) {
        cudaFuncSetAttribute(gca_fused_kernel,
                             cudaFuncAttributeMaxDynamicSharedMemorySize, SMEM_BYTES);
        attr_set = true;
    }

    seg_bounds_kernel<<<(Bn + THREADS) / THREADS + 1, 256>>>(idx, Fn, Bn);
    dim3 grid(Bn, Jn);
    gca_fused_kernel<<<grid, THREADS, SMEM_BYTES>>>(x, W, out, Jn, Fn, Bn);
}